// round 17
// baseline (speedup 1.0000x reference)
#include <cuda_runtime.h>
#include <cuda_bf16.h>
#include <math.h>
#include <stdint.h>

typedef unsigned long long ull;

#define BATCH 64
#define LSEQ  2048
#define DMODEL 256
#define DU 1024
#define HHID 128
#define NTOK (BATCH*LSEQ)
#define LTOK 64
#define NT2 (NTOK/LTOK)   // 2048

// ---------------- device scratch ----------------
__device__ __nv_bfloat16 g_hev_hi[(size_t)NTOK * DMODEL];
__device__ __nv_bfloat16 g_hev_lo[(size_t)NTOK * DMODEL];
__device__ float g_cvec[HHID];
__device__ float g_aval[NTOK];
__device__ int   g_active[NTOK];
__device__ int   g_count[BATCH];
__device__ int   g_tile;
__device__ int   g_work;

// ---------------- helpers ----------------
__device__ __forceinline__ float lrelu(float x) { return x > 0.f ? x : 0.2f * x; }

__device__ __forceinline__ uint32_t smem_u32(const void* p) {
    uint32_t a;
    asm("{ .reg .u64 t; cvta.to.shared.u64 t, %1; cvt.u32.u64 %0, t; }" : "=r"(a) : "l"(p));
    return a;
}
__device__ __forceinline__ void mma16816(float* d, const uint32_t* a, const uint32_t* b) {
    asm volatile(
        "mma.sync.aligned.m16n8k16.row.col.f32.bf16.bf16.f32 "
        "{%0,%1,%2,%3}, {%4,%5,%6,%7}, {%8,%9}, {%0,%1,%2,%3};"
        : "+f"(d[0]), "+f"(d[1]), "+f"(d[2]), "+f"(d[3])
        : "r"(a[0]), "r"(a[1]), "r"(a[2]), "r"(a[3]), "r"(b[0]), "r"(b[1]));
}
__device__ __forceinline__ void ldsm4(uint32_t* r, uint32_t addr) {
    asm volatile("ldmatrix.sync.aligned.m8n8.x4.shared.b16 {%0,%1,%2,%3}, [%4];"
        : "=r"(r[0]), "=r"(r[1]), "=r"(r[2]), "=r"(r[3]) : "r"(addr));
}
__device__ __forceinline__ void cp16(uint32_t dst, const void* src) {
    asm volatile("cp.async.cg.shared.global [%0], [%1], 16;" :: "r"(dst), "l"(src));
}
#define CP_COMMIT() asm volatile("cp.async.commit_group;" ::: "memory")
#define CP_WAIT0()  asm volatile("cp.async.wait_group 0;" ::: "memory")
#define CP_WAIT1()  asm volatile("cp.async.wait_group 1;" ::: "memory")

__device__ __forceinline__ uint32_t pack_bf16x2(float lo, float hi) {
    __nv_bfloat162 p = __floats2bfloat162_rn(lo, hi);
    uint32_t u; memcpy(&u, &p, 4); return u;
}
// split float4 into hi/lo bf16x2 pairs (uint2 each)
__device__ __forceinline__ void split4(float4 v, uint2* hi, uint2* lo) {
    float h0 = __bfloat162float(__float2bfloat16(v.x));
    float h1 = __bfloat162float(__float2bfloat16(v.y));
    float h2 = __bfloat162float(__float2bfloat16(v.z));
    float h3 = __bfloat162float(__float2bfloat16(v.w));
    hi->x = pack_bf16x2(h0, h1);
    hi->y = pack_bf16x2(h2, h3);
    lo->x = pack_bf16x2(v.x - h0, v.y - h1);
    lo->y = pack_bf16x2(v.z - h2, v.w - h3);
}

// ---------------- kernel 0: small init (zero outputs, counters, cvec) ----------------
__global__ __launch_bounds__(256) void k_init(
    const float* __restrict__ Ws1, const float* __restrict__ bs1,
    const float* __restrict__ vn, float* __restrict__ out_u)
{
    const int bid = blockIdx.x;
    const int tid = threadIdx.x;
    if (bid < 256) {
        int idx = bid * 256 + tid;
        out_u[idx] = 0.f;                    // 64*1024 = 65536 = 256*256
        if (idx < BATCH) g_count[idx] = 0;
        if (idx == 0) { g_tile = 0; g_work = 0; }
    } else {
        int h = (bid - 256) * 8 + (tid >> 5);  // 16 blocks x 8 warps = 128 h
        int l = tid & 31;
        if (h >= HHID) return;
        const float* row = Ws1 + (size_t)h * 512 + 256;
        float s = 0.f;
#pragma unroll
        for (int d = l; d < 256; d += 32) s += row[d] * vn[d];
#pragma unroll
        for (int off = 16; off; off >>= 1) s += __shfl_xor_sync(0xffffffffu, s, off);
        if (l == 0) g_cvec[h] = s + bs1[h];
    }
}

// ---------------- kernel 1a: embedding + sincos -> bf16 hi/lo ----------------
__global__ __launch_bounds__(256) void k_emb(
    const int* __restrict__ q_seq, const int* __restrict__ r_seq,
    const float* __restrict__ t_seq,
    const float* __restrict__ q_tab, const float* __restrict__ r_tab)
{
    __shared__ int sq[32], sr[32];
    __shared__ float st[32];
    const int tid = threadIdx.x;
    const int tok0 = blockIdx.x * 32;
    if (tid < 32) {
        sq[tid] = q_seq[tok0 + tid];
        sr[tid] = r_seq[tok0 + tid];
        st[tid] = t_seq[tok0 + tid];
    }
    __syncthreads();
    const int dp   = tid & 63;
    const int tseg = tid >> 6;          // 0..3 -> 8 tokens each
    const int d0   = dp * 2;            // 0..126
    const float KF = -9.2103403719761836f / 128.f;
    const float f0 = expf((float)d0 * KF);
    const float f1 = expf((float)(d0 + 1) * KF);
    uint32_t* ghw = (uint32_t*)(g_hev_hi + (((size_t)tok0 + tseg * 8) << 8) + d0);
    uint32_t* glw = (uint32_t*)(g_hev_lo + (((size_t)tok0 + tseg * 8) << 8) + d0);
#pragma unroll 2
    for (int t = 0; t < 8; ++t) {
        int tok = tseg * 8 + t;
        float tv = st[tok];
        float s0, c0, s1, c1;
        sincosf(tv * f0, &s0, &c0);
        sincosf(tv * f1, &s1, &c1);
        const float* qrow = q_tab + (size_t)sq[tok] * 256 + d0;
        const float* rrow = r_tab + (size_t)sr[tok] * 256 + d0;
        const float2 qa = *(const float2*)qrow;
        const float2 ra = *(const float2*)rrow;
        const float2 qb = *(const float2*)(qrow + 128);
        const float2 rb = *(const float2*)(rrow + 128);
        float v0 = qa.x + ra.x + s0;
        float v1 = qa.y + ra.y + s1;
        float v2 = qb.x + rb.x + c0;
        float v3 = qb.y + rb.y + c1;
        float h0f = __bfloat162float(__float2bfloat16(v0));
        float h1f = __bfloat162float(__float2bfloat16(v1));
        float h2f = __bfloat162float(__float2bfloat16(v2));
        float h3f = __bfloat162float(__float2bfloat16(v3));
        size_t off = (size_t)t << 7;
        ghw[off]      = pack_bf16x2(h0f, h1f);
        ghw[off + 64] = pack_bf16x2(h2f, h3f);
        glw[off]      = pack_bf16x2(v0 - h0f, v1 - h1f);
        glw[off + 64] = pack_bf16x2(v2 - h2f, v3 - h3f);
    }
}

// ---------------- kernel 1b: pipelined HMMA logits (512 thr, reversed tiles) ----------------
#define LW_OFF   0
#define LW_TERM  67584
#define LH_OFF   135168
#define LH_BUF   34816
#define LH_TERM  17408
#define LSLOG    204800
#define LSTILE   205824
#define SMEM_LG  205952

__global__ __launch_bounds__(512, 1) void k_logits_mma(
    const float* __restrict__ mask, const float* __restrict__ Ws1,
    const float* __restrict__ Ws2, const float* __restrict__ bs2,
    float* __restrict__ outA)
{
    extern __shared__ char smem[];
    const uint32_t sb = smem_u32(smem);
    const int tid  = threadIdx.x;
    const int wid  = tid >> 5;
    const int lane = tid & 31;
    const int gid  = lane >> 2;
    const int warpM = wid >> 2;
    const int warpN = wid & 3;

    float* slog  = (float*)(smem + LSLOG);
    int*   stile = (int*)(smem + LSTILE);

    // stage Ws1[:,0:256] fp32 -> bf16 hi/lo smem (split on stage)
    for (int i = tid; i < 8192; i += 512) {
        int r = i >> 6;           // h row 0..127
        int c = i & 63;           // float4 group 0..63
        float4 v = *(const float4*)(Ws1 + (size_t)r * 512 + c * 4);
        uint2 hi, lo;
        split4(v, &hi, &lo);
        *(uint2*)(smem + LW_OFF + r * 528 + c * 8) = hi;
        *(uint2*)(smem + LW_OFF + LW_TERM + r * 528 + c * 8) = lo;
    }

    float wc[2][2], cv[2][2];
#pragma unroll
    for (int m = 0; m < 2; ++m) {
        int h0 = warpM * 32 + m * 16 + gid;
        wc[m][0] = Ws2[h0];     wc[m][1] = Ws2[h0 + 8];
        cv[m][0] = g_cvec[h0];  cv[m][1] = g_cvec[h0 + 8];
    }
    const float b2v = bs2[0];

    const uint32_t w_ld = sb + LW_OFF + (uint32_t)((lane & 15) * 528 + (lane >> 4) * 16);
    const uint32_t h_ld = sb + LH_OFF +
        (uint32_t)((warpN * 16 + (lane & 15)) * 272 + (lane >> 4) * 16);

    if (tid == 0) *stile = atomicAdd(&g_tile, 1);
    __syncthreads();
    int tctr = *stile;
    int tile = NT2 - 1 - tctr;

    if (tctr < NT2) {
#pragma unroll
        for (int i = 0; i < 4; ++i) {
            int idx = tid + i * 512;
            int term = idx >> 10;
            int row  = (idx >> 4) & 63;
            int c    = idx & 15;
            const __nv_bfloat16* src = term ? g_hev_lo : g_hev_hi;
            cp16(sb + LH_OFF + (uint32_t)(term * LH_TERM + row * 272 + c * 16),
                 src + (((size_t)(tile * LTOK + row)) << 8) + (c << 3));
        }
        CP_COMMIT();
    }

    while (tctr < NT2) {
        const int tok0 = tile * LTOK;
        const int b    = tok0 >> 11;

#pragma unroll
        for (int i = 0; i < 4; ++i) {
            int idx = tid + i * 512;
            int term = idx >> 10;
            int row  = (idx >> 4) & 63;
            int c    = idx & 15;
            const __nv_bfloat16* src = term ? g_hev_lo : g_hev_hi;
            cp16(sb + LH_OFF + LH_BUF + (uint32_t)(term * LH_TERM + row * 272 + c * 16),
                 src + (((size_t)(tok0 + row)) << 8) + 128 + (c << 3));
        }
        CP_COMMIT();
        if (tid == 0) *stile = atomicAdd(&g_tile, 1);

        CP_WAIT1();
        __syncthreads();

        float C[2][2][4], D[2][2][4];
#pragma unroll
        for (int m = 0; m < 2; ++m)
#pragma unroll
            for (int n = 0; n < 2; ++n)
#pragma unroll
                for (int k = 0; k < 4; ++k) { C[m][n][k] = 0.f; D[m][n][k] = 0.f; }

#pragma unroll
        for (int ks = 0; ks < 8; ++ks) {
            uint32_t ah[2][4], al[2][4], bh[2][2], bl[2][2], tmp[4];
#pragma unroll
            for (int m = 0; m < 2; ++m) {
                uint32_t ro = (uint32_t)((warpM * 32 + m * 16) * 528 + ks * 32);
                ldsm4(ah[m], w_ld + ro);
                ldsm4(al[m], w_ld + LW_TERM + ro);
            }
            {
                uint32_t no = (uint32_t)(ks * 32);
                ldsm4(tmp, h_ld + no);
                bh[0][0] = tmp[0]; bh[1][0] = tmp[1];
                bh[0][1] = tmp[2]; bh[1][1] = tmp[3];
                ldsm4(tmp, h_ld + LH_TERM + no);
                bl[0][0] = tmp[0]; bl[1][0] = tmp[1];
                bl[0][1] = tmp[2]; bl[1][1] = tmp[3];
            }
#pragma unroll
            for (int m = 0; m < 2; ++m)
#pragma unroll
                for (int n = 0; n < 2; ++n) mma16816(C[m][n], ah[m], bh[n]);
#pragma unroll
            for (int m = 0; m < 2; ++m)
#pragma unroll
                for (int n = 0; n < 2; ++n) mma16816(D[m][n], ah[m], bl[n]);
#pragma unroll
            for (int m = 0; m < 2; ++m)
#pragma unroll
                for (int n = 0; n < 2; ++n) mma16816(C[m][n], al[m], bh[n]);
        }
        __syncthreads();

        const int nctr = *stile;
        const int ntile = NT2 - 1 - nctr;
        if (nctr < NT2) {
#pragma unroll
            for (int i = 0; i < 4; ++i) {
                int idx = tid + i * 512;
                int term = idx >> 10;
                int row  = (idx >> 4) & 63;
                int c    = idx & 15;
                const __nv_bfloat16* src = term ? g_hev_lo : g_hev_hi;
                cp16(sb + LH_OFF + (uint32_t)(term * LH_TERM + row * 272 + c * 16),
                     src + (((size_t)(ntile * LTOK + row)) << 8) + (c << 3));
            }
            CP_COMMIT();
            CP_WAIT1();
        } else {
            CP_WAIT0();
        }
        __syncthreads();

#pragma unroll
        for (int ks = 0; ks < 8; ++ks) {
            uint32_t ah[2][4], al[2][4], bh[2][2], bl[2][2], tmp[4];
#pragma unroll
            for (int m = 0; m < 2; ++m) {
                uint32_t ro = (uint32_t)((warpM * 32 + m * 16) * 528 + (8 + ks) * 32);
                ldsm4(ah[m], w_ld + ro);
                ldsm4(al[m], w_ld + LW_TERM + ro);
            }
            {
                uint32_t no = (uint32_t)(LH_BUF + ks * 32);
                ldsm4(tmp, h_ld + no);
                bh[0][0] = tmp[0]; bh[1][0] = tmp[1];
                bh[0][1] = tmp[2]; bh[1][1] = tmp[3];
                ldsm4(tmp, h_ld + LH_TERM + no);
                bl[0][0] = tmp[0]; bl[1][0] = tmp[1];
                bl[0][1] = tmp[2]; bl[1][1] = tmp[3];
            }
#pragma unroll
            for (int m = 0; m < 2; ++m)
#pragma unroll
                for (int n = 0; n < 2; ++n) mma16816(C[m][n], ah[m], bh[n]);
#pragma unroll
            for (int m = 0; m < 2; ++m)
#pragma unroll
                for (int n = 0; n < 2; ++n) mma16816(D[m][n], ah[m], bl[n]);
#pragma unroll
            for (int m = 0; m < 2; ++m)
#pragma unroll
                for (int n = 0; n < 2; ++n) mma16816(C[m][n], al[m], bh[n]);
        }

        {
            float tsum[2][2];
#pragma unroll
            for (int n = 0; n < 2; ++n) { tsum[n][0] = 0.f; tsum[n][1] = 0.f; }
#pragma unroll
            for (int m = 0; m < 2; ++m)
#pragma unroll
                for (int n = 0; n < 2; ++n) {
                    float e0 = C[m][n][0] + D[m][n][0];
                    float e1 = C[m][n][1] + D[m][n][1];
                    float e2 = C[m][n][2] + D[m][n][2];
                    float e3 = C[m][n][3] + D[m][n][3];
                    tsum[n][0] += wc[m][0] * lrelu(e0 + cv[m][0])
                                + wc[m][1] * lrelu(e2 + cv[m][1]);
                    tsum[n][1] += wc[m][0] * lrelu(e1 + cv[m][0])
                                + wc[m][1] * lrelu(e3 + cv[m][1]);
                }
#pragma unroll
            for (int n = 0; n < 2; ++n)
#pragma unroll
                for (int k2 = 0; k2 < 2; ++k2) {
                    float v = tsum[n][k2];
                    v += __shfl_xor_sync(0xffffffffu, v, 4);
                    v += __shfl_xor_sync(0xffffffffu, v, 8);
                    v += __shfl_xor_sync(0xffffffffu, v, 16);
                    tsum[n][k2] = v;
                }
            if (lane < 4) {
#pragma unroll
                for (int n = 0; n < 2; ++n) {
                    int t = warpN * 16 + n * 8 + 2 * lane;
                    slog[warpM * 64 + t]     = tsum[n][0];
                    slog[warpM * 64 + t + 1] = tsum[n][1];
                }
            }
        }
        __syncthreads();

        if (tid < 64) {
            float logit = slog[tid] + slog[64 + tid] + slog[128 + tid]
                        + slog[192 + tid] + b2v;
            float a = mask[tok0 + tid] / (1.f + expf(-logit * 100.f));
            outA[tok0 + tid]   = a;
            g_aval[tok0 + tid] = a;
            bool act = a > 1e-10f;
            unsigned mb = __ballot_sync(0xffffffffu, act);
            int cntw = __popc(mb);
            int base = 0;
            if (lane == 0 && cntw) base = atomicAdd(&g_count[b], cntw);
            base = __shfl_sync(0xffffffffu, base, 0);
            if (act) {
                int slot = base + __popc(mb & ((1u << lane) - 1u));
                g_active[b * LSEQ + slot] = (tok0 & (LSEQ - 1)) + tid;
            }
        }
        tctr = nctr;
        tile = ntile;
        __syncthreads();
    }
}

// ---------------- kernel 2: persistent dynamic HMMA aggregator ----------------
#define KA_B_OFF   0
#define KA_A_OFF   135168
#define KA_ABUF    34816
#define KA_ATERM   17408
#define KA_SA_OFF  204800
#define KA_STOK_OFF 205312
#define KA_SWORK   205824
#define SMEM_AGG   205952

__global__ __launch_bounds__(512, 1) void k_agg_p(const float* __restrict__ Wa,
                                                  const float* __restrict__ ba,
                                                  float* __restrict__ out_u)
{
    extern __shared__ char smem[];
    const uint32_t sb = smem_u32(smem);
    const int tid  = threadIdx.x;
    const int wid  = tid >> 5;
    const int lane = tid & 31;
    const int gid  = lane >> 2;
    const int warpM = wid >> 2;
    const int warpN = wid & 3;

    float* sa    = (float*)(smem + KA_SA_OFF);
    int*   stok  = (int*)(smem + KA_STOK_OFF);
    int*   swork = (int*)(smem + KA_SWORK);

    const uint32_t a_ld_base = sb + KA_A_OFF
        + (uint32_t)((lane & 15) * 272 + (lane >> 4) * 16);
    const uint32_t b_ld_base = sb + KA_B_OFF
        + (uint32_t)((warpN * 32 + (lane & 15)) * 528 + (lane >> 4) * 16);

    int cached_ucol = -1;
    float ban0[4], ban1[4];

    while (true) {
        if (tid == 0) *swork = atomicAdd(&g_work, 1);
        __syncthreads();
        const int w = *swork;
        if (w >= 512) break;
        const int ucol = w >> 6;
        const int b    = w & 63;
        const int colbase = ucol * 128;

        if (ucol != cached_ucol) {
            __syncthreads();
            // stage B: Wa fp32 rows -> bf16 hi/lo smem (split on stage)
            for (int i = tid; i < 8192; i += 512) {
                int r = i >> 6;       // row 0..127
                int c = i & 63;       // float4 group
                float4 v = *(const float4*)(Wa + (size_t)(colbase + r) * 256 + c * 4);
                uint2 hi, lo;
                split4(v, &hi, &lo);
                *(uint2*)(smem + KA_B_OFF + r * 528 + c * 8) = hi;
                *(uint2*)(smem + KA_B_OFF + 67584 + r * 528 + c * 8) = lo;
            }
#pragma unroll
            for (int n = 0; n < 4; ++n) {
                int c0 = colbase + warpN * 32 + n * 8 + 2 * (lane & 3);
                ban0[n] = ba[c0];
                ban1[n] = ba[c0 + 1];
            }
            cached_ucol = ucol;
        }

        const int cnt = g_count[b];
        const int ntile = (cnt + 63) >> 6;

        __syncthreads();

        float colacc[4][2];
#pragma unroll
        for (int n = 0; n < 4; ++n) { colacc[n][0] = 0.f; colacc[n][1] = 0.f; }

        if (tid < 64 && ntile > 0) {
            int tok = (tid < cnt) ? g_active[(b << 11) + tid] : 0;
            stok[tid] = tok;
            sa[tid]   = (tid < cnt) ? g_aval[(b << 11) + tok] : 0.f;
        }
        __syncthreads();

        if (ntile > 0) {
#pragma unroll
            for (int i = 0; i < 4; ++i) {
                int idx = tid + i * 512;
                int term = idx >> 10;
                int row  = (idx >> 4) & 63;
                int c    = idx & 15;
                const __nv_bfloat16* src = term ? g_hev_lo : g_hev_hi;
                cp16(sb + KA_A_OFF + (uint32_t)(term * KA_ATERM + row * 272 + c * 16),
                     src + (((size_t)(b << 11) + stok[row]) << 8) + (c << 3));
            }
            CP_COMMIT();
        }

        int cur = 0;
        for (int t = 0; t < ntile; ++t, cur ^= 1) {
            const int nxt = cur ^ 1;
            if (tid < 64 && t + 1 < ntile) {
                int slot = ((t + 1) << 6) + tid;
                int tok = (slot < cnt) ? g_active[(b << 11) + slot] : 0;
                stok[nxt * 64 + tid] = tok;
                sa[nxt * 64 + tid]   = (slot < cnt) ? g_aval[(b << 11) + tok] : 0.f;
            }
            CP_WAIT0();
            __syncthreads();

#pragma unroll
            for (int i = 0; i < 4; ++i) {
                int idx = tid + i * 512;
                int term = idx >> 10;
                int row  = (idx >> 4) & 63;
                int c    = idx & 15;
                const __nv_bfloat16* src = term ? g_hev_lo : g_hev_hi;
                cp16(sb + KA_A_OFF + KA_ABUF
                         + (uint32_t)(term * KA_ATERM + row * 272 + c * 16),
                     src + (((size_t)(b << 11) + stok[cur * 64 + row]) << 8) + 128 + (c << 3));
            }
            CP_COMMIT();

            float C[4][4], D[4][4];
#pragma unroll
            for (int n = 0; n < 4; ++n)
#pragma unroll
                for (int k = 0; k < 4; ++k) { C[n][k] = 0.f; D[n][k] = 0.f; }

#pragma unroll
            for (int ks = 0; ks < 8; ++ks) {
                uint32_t ah[4], al[4], bh[4][2], bl[4][2], tmp[4];
                {
                    uint32_t ro = (uint32_t)((warpM * 16) * 272 + ks * 32);
                    ldsm4(ah, a_ld_base + ro);
                    ldsm4(al, a_ld_base + KA_ATERM + ro);
                }
#pragma unroll
                for (int nc = 0; nc < 2; ++nc) {
                    uint32_t no = (uint32_t)(nc * 16 * 528 + ks * 32);
                    ldsm4(tmp, b_ld_base + no);
                    bh[2*nc][0] = tmp[0]; bh[2*nc+1][0] = tmp[1];
                    bh[2*nc][1] = tmp[2]; bh[2*nc+1][1] = tmp[3];
                    ldsm4(tmp, b_ld_base + 67584 + no);
                    bl[2*nc][0] = tmp[0]; bl[2*nc+1][0] = tmp[1];
                    bl[2*nc][1] = tmp[2]; bl[2*nc+1][1] = tmp[3];
                }
#pragma unroll
                for (int n = 0; n < 4; ++n) mma16816(C[n], ah, bh[n]);
#pragma unroll
                for (int n = 0; n < 4; ++n) mma16816(D[n], ah, bl[n]);
#pragma unroll
                for (int n = 0; n < 4; ++n) mma16816(C[n], al, bh[n]);
            }

            CP_WAIT0();
            __syncthreads();

            if (t + 1 < ntile) {
#pragma unroll
                for (int i = 0; i < 4; ++i) {
                    int idx = tid + i * 512;
                    int term = idx >> 10;
                    int row  = (idx >> 4) & 63;
                    int c    = idx & 15;
                    const __nv_bfloat16* src = term ? g_hev_lo : g_hev_hi;
                    cp16(sb + KA_A_OFF + (uint32_t)(term * KA_ATERM + row * 272 + c * 16),
                         src + (((size_t)(b << 11) + stok[nxt * 64 + row]) << 8) + (c << 3));
                }
                CP_COMMIT();
            }

#pragma unroll
            for (int ks = 0; ks < 8; ++ks) {
                uint32_t ah[4], al[4], bh[4][2], bl[4][2], tmp[4];
                {
                    uint32_t ro = (uint32_t)((warpM * 16) * 272 + ks * 32);
                    ldsm4(ah, a_ld_base + KA_ABUF + ro);
                    ldsm4(al, a_ld_base + KA_ABUF + KA_ATERM + ro);
                }
#pragma unroll
                for (int nc = 0; nc < 2; ++nc) {
                    uint32_t no = (uint32_t)(nc * 16 * 528 + 256 + ks * 32);
                    ldsm4(tmp, b_ld_base + no);
                    bh[2*nc][0] = tmp[0]; bh[2*nc+1][0] = tmp[1];
                    bh[2*nc][1] = tmp[2]; bh[2*nc+1][1] = tmp[3];
                    ldsm4(tmp, b_ld_base + 67584 + no);
                    bl[2*nc][0] = tmp[0]; bl[2*nc+1][0] = tmp[1];
                    bl[2*nc][1] = tmp[2]; bl[2*nc+1][1] = tmp[3];
                }
#pragma unroll
                for (int n = 0; n < 4; ++n) mma16816(C[n], ah, bh[n]);
#pragma unroll
                for (int n = 0; n < 4; ++n) mma16816(D[n], ah, bl[n]);
#pragma unroll
                for (int n = 0; n < 4; ++n) mma16816(C[n], al, bh[n]);
            }

            {
                float a0 = sa[cur * 64 + warpM * 16 + gid];
                float a1 = sa[cur * 64 + warpM * 16 + gid + 8];
#pragma unroll
                for (int n = 0; n < 4; ++n) {
                    float e0 = C[n][0] + D[n][0];
                    float e1 = C[n][1] + D[n][1];
                    float e2 = C[n][2] + D[n][2];
                    float e3 = C[n][3] + D[n][3];
                    colacc[n][0] += a0 * lrelu(e0 + ban0[n])
                                  + a1 * lrelu(e2 + ban0[n]);
                    colacc[n][1] += a0 * lrelu(e1 + ban1[n])
                                  + a1 * lrelu(e3 + ban1[n]);
                }
            }
        }

#pragma unroll
        for (int n = 0; n < 4; ++n)
#pragma unroll
            for (int j = 0; j < 2; ++j) {
                float v = colacc[n][j];
                v += __shfl_xor_sync(0xffffffffu, v, 4);
                v += __shfl_xor_sync(0xffffffffu, v, 8);
                v += __shfl_xor_sync(0xffffffffu, v, 16);
                colacc[n][j] = v;
            }
        if (lane < 4) {
#pragma unroll
            for (int n = 0; n < 4; ++n) {
                int c0 = colbase + warpN * 32 + n * 8 + 2 * lane;
                atomicAdd(&out_u[b * DU + c0],     colacc[n][0]);
                atomicAdd(&out_u[b * DU + c0 + 1], colacc[n][1]);
            }
        }
    }
}

// ---------------- launch ----------------
extern "C" void kernel_launch(void* const* d_in, const int* in_sizes, int n_in,
                              void* d_out, int out_size) {
    const int*   q_seq = (const int*)d_in[0];
    const int*   r_seq = (const int*)d_in[1];
    const float* t_seq = (const float*)d_in[2];
    const float* mask  = (const float*)d_in[3];
    const float* q_tab = (const float*)d_in[4];
    const float* r_tab = (const float*)d_in[5];
    const float* vn    = (const float*)d_in[6];
    const float* Ws1   = (const float*)d_in[7];
    const float* bs1   = (const float*)d_in[8];
    const float* Ws2   = (const float*)d_in[9];
    const float* bs2   = (const float*)d_in[10];
    const float* Wa    = (const float*)d_in[11];
    const float* ba    = (const float*)d_in[12];

    float* out_u = (float*)d_out;            // (64, 1024)
    float* outA  = out_u + BATCH * DU;       // (64, 2048)

    k_init<<<272, 256>>>(Ws1, bs1, vn, out_u);

    k_emb<<<NTOK / 32, 256>>>(q_seq, r_seq, t_seq, q_tab, r_tab);

    cudaFuncSetAttribute(k_logits_mma, cudaFuncAttributeMaxDynamicSharedMemorySize, SMEM_LG);
    k_logits_mma<<<148, 512, SMEM_LG>>>(mask, Ws1, Ws2, bs2, outA);

    cudaFuncSetAttribute(k_agg_p, cudaFuncAttributeMaxDynamicSharedMemorySize, SMEM_AGG);
    k_agg_p<<<148, 512, SMEM_AGG>>>(Wa, ba, out_u);
}